// round 1
// baseline (speedup 1.0000x reference)
#include <cuda_runtime.h>
#include <math.h>

#define NB 64
#define TT 256
#define INDIM 512
#define HH 1024
#define G3 (3*HH)   // packed gate columns: [i (0:H), g (H:2H), o (2H:3H)] -- f gate skipped (unused in reference)

// Scratch (static device memory only -- no allocations allowed)
__device__ float g_gx0[(size_t)NB * TT * G3];   // precomputed x@Wx0^T + b0, packed cols
__device__ float g_h0[2][NB * HH];              // ping-pong h for layer 0
__device__ float g_h1[2][NB * HH];              // ping-pong h for layer 1
__device__ float g_c0[NB * HH];
__device__ float g_c1[NB * HH];

__device__ __forceinline__ float sigmoid_(float x) {
    return 1.0f / (1.0f + expf(-x));
}
__device__ __forceinline__ float tanh_(float x) {
    // accurate tanh from exp (avoid MUFU.TANH's 2^-11 error compounding over 256 steps)
    return 1.0f - 2.0f / (expf(2.0f * x) + 1.0f);
}

__global__ void init_state() {
    int i = blockIdx.x * blockDim.x + threadIdx.x;
    if (i < NB * HH) {
        g_h0[0][i] = 0.f; g_h0[1][i] = 0.f;
        g_h1[0][i] = 0.f; g_h1[1][i] = 0.f;
        g_c0[i] = 0.f;    g_c1[i] = 0.f;
    }
}

// ---------------------------------------------------------------------------
// Precompute gx0[nt][jj] = b0[m(jj)] + sum_k x[nt][k] * Wx0[m(jj)][k]
// jj in [0, 3072): m(jj) = jj            for jj <  1024  (i gate)
//                  m(jj) = jj + 1024     for jj >= 1024  (g: rows 2048.., o: rows 3072..)
// CTA tile 128 rows x 64 cols, K-chunk 16, 256 threads, 8x4 register tiles.
// ---------------------------------------------------------------------------
__global__ __launch_bounds__(256) void precompute_gx0(
    const float* __restrict__ x, const float* __restrict__ Wx0,
    const float* __restrict__ b0)
{
    __shared__ float sx[128 * 17];
    __shared__ float sw[64 * 17];
    const int row0 = blockIdx.x * 128;
    const int col0 = blockIdx.y * 64;
    const int tid = threadIdx.x;
    const int ty = tid >> 4;   // 0..15 (row groups of 8)
    const int tx = tid & 15;   // 0..15 (col groups of 4)

    float acc[8][4];
#pragma unroll
    for (int i = 0; i < 8; i++)
#pragma unroll
        for (int j = 0; j < 4; j++) acc[i][j] = 0.f;

    for (int k0 = 0; k0 < INDIM; k0 += 16) {
        // x tile: 128 x 16 (float4 gmem loads, scalar padded SMEM stores)
#pragma unroll
        for (int it = 0; it < 2; it++) {
            int lin = tid + it * 256;            // float4 index 0..511
            int r = lin >> 2;
            int kq = (lin & 3) << 2;
            float4 v = *reinterpret_cast<const float4*>(
                &x[(size_t)(row0 + r) * INDIM + k0 + kq]);
            float* d = &sx[r * 17 + kq];
            d[0] = v.x; d[1] = v.y; d[2] = v.z; d[3] = v.w;
        }
        // w tile: 64 cols x 16
#pragma unroll
        for (int it = 0; it < 4; it++) {
            int lin = tid + it * 256;            // 0..1023
            int c = lin >> 4;
            int k = lin & 15;
            int jj = col0 + c;
            int wrow = jj + ((jj >= HH) ? HH : 0);
            sw[c * 17 + k] = Wx0[(size_t)wrow * INDIM + k0 + k];
        }
        __syncthreads();
#pragma unroll
        for (int kk = 0; kk < 16; kk++) {
            float xr[8], wr[4];
#pragma unroll
            for (int i = 0; i < 8; i++) xr[i] = sx[(ty * 8 + i) * 17 + kk];
#pragma unroll
            for (int j = 0; j < 4; j++) wr[j] = sw[(tx * 4 + j) * 17 + kk];
#pragma unroll
            for (int i = 0; i < 8; i++)
#pragma unroll
                for (int j = 0; j < 4; j++) acc[i][j] += xr[i] * wr[j];
        }
        __syncthreads();
    }
#pragma unroll
    for (int j = 0; j < 4; j++) {
        int jj = col0 + tx * 4 + j;
        int wrow = jj + ((jj >= HH) ? HH : 0);
        float bias = b0[wrow];
#pragma unroll
        for (int i = 0; i < 8; i++) {
            int r = row0 + ty * 8 + i;
            g_gx0[(size_t)r * G3 + jj] = acc[i][j] + bias;
        }
    }
}

// ---------------------------------------------------------------------------
// One recurrent step for one layer.
//   layer 0: gates = gx0[n,t,:] + h0_old @ Wh0^T          (K = 1024)
//   layer 1: gates = b1 + h0_new @ Wx1^T + h1_old @ Wh1^T (K = 2048, two phases)
// Then pointwise (faithful to reference bugs):
//   i = sig(gi + Wc[0]*c); g = tanh(gg); o = sig(go + Wc[2]*c)
//   c_new = g*(c + i);  h_new = o*tanh(c_old)
// Grid: 128 CTAs x 8 hidden units; CTA computes 64 batch x (8 units x 3 gates).
// 128 threads, 4 batch x 3 gate register tiles.
// ---------------------------------------------------------------------------
template <int LAYER>
__global__ __launch_bounds__(128) void lstm_step(
    const float* __restrict__ Wh,    // layer0: Wh0, layer1: Wh1 [4096,1024]
    const float* __restrict__ Wx1,   // layer1 only [4096,1024]
    const float* __restrict__ bias,  // layer1: b1 [4096] (layer0 bias folded into gx0)
    const float* __restrict__ Wc,    // [3,1024]
    float* __restrict__ out, int t)
{
    __shared__ float sh[64 * 33];    // h tile 64 x 32 (+pad)
    __shared__ float sw[24 * 33];    // weight rows: [gate q 0..2][unit u 0..7] x 32 (+pad)

    const int tid = threadIdx.x;
    const int ty = tid >> 3;   // 0..15 batch groups (4 each)
    const int tz = tid & 7;    // 0..7 local unit
    const int u0 = blockIdx.x * 8;
    const int rd = t & 1;           // parity of h buffers to read
    const int wr = (t + 1) & 1;     // parity to write

    float acc[4][3];
#pragma unroll
    for (int i = 0; i < 4; i++)
#pragma unroll
        for (int q = 0; q < 3; q++) acc[i][q] = 0.f;

    const int nPhase = (LAYER == 0) ? 1 : 2;
    for (int ph = 0; ph < nPhase; ph++) {
        const float* hsrc = (LAYER == 0) ? g_h0[rd]
                                         : (ph == 0 ? g_h0[wr] : g_h1[rd]);
        const float* W = (LAYER == 0) ? Wh : (ph == 0 ? Wx1 : Wh);
        for (int k0 = 0; k0 < HH; k0 += 32) {
            // h tile 64x32 (float4 gmem loads)
#pragma unroll
            for (int it = 0; it < 4; it++) {
                int lin = tid + it * 128;        // float4 idx 0..511
                int b = lin >> 3;
                int kq = (lin & 7) << 2;
                float4 v = *reinterpret_cast<const float4*>(
                    &hsrc[b * HH + k0 + kq]);
                float* d = &sh[b * 33 + kq];
                d[0] = v.x; d[1] = v.y; d[2] = v.z; d[3] = v.w;
            }
            // w tile 24x32: row r = q*8 + u
#pragma unroll
            for (int it = 0; it < 6; it++) {
                int lin = tid + it * 128;        // 0..767
                int r = lin >> 5;
                int k = lin & 31;
                int q = r >> 3;
                int u = r & 7;
                int grow = (u0 + u) + (q ? (q + 1) * HH : 0);  // i: j, g: 2H+j, o: 3H+j
                sw[r * 33 + k] = W[(size_t)grow * HH + k0 + k];
            }
            __syncthreads();
#pragma unroll 8
            for (int kk = 0; kk < 32; kk++) {
                float hr[4], wreg[3];
#pragma unroll
                for (int i = 0; i < 4; i++) hr[i] = sh[(ty * 4 + i) * 33 + kk];
#pragma unroll
                for (int q = 0; q < 3; q++) wreg[q] = sw[(q * 8 + tz) * 33 + kk];
#pragma unroll
                for (int i = 0; i < 4; i++)
#pragma unroll
                    for (int q = 0; q < 3; q++) acc[i][q] += hr[i] * wreg[q];
            }
            __syncthreads();
        }
    }

    // pointwise
    const int j = u0 + tz;
    const float wci = Wc[j];
    const float wco = Wc[2 * HH + j];
    float* hdst = (LAYER == 0) ? g_h0[wr] : g_h1[wr];
    float* cbuf = (LAYER == 0) ? g_c0 : g_c1;
#pragma unroll
    for (int i = 0; i < 4; i++) {
        int b = ty * 4 + i;
        float pre_i, pre_g, pre_o;
        if (LAYER == 0) {
            const float* gx = &g_gx0[((size_t)b * TT + t) * G3];
            pre_i = acc[i][0] + gx[j];
            pre_g = acc[i][1] + gx[HH + j];
            pre_o = acc[i][2] + gx[2 * HH + j];
        } else {
            pre_i = acc[i][0] + bias[j];
            pre_g = acc[i][1] + bias[2 * HH + j];
            pre_o = acc[i][2] + bias[3 * HH + j];
        }
        float c = cbuf[b * HH + j];
        float ig = sigmoid_(pre_i + wci * c);
        float gg = tanh_(pre_g);
        float og = sigmoid_(pre_o + wco * c);
        float cn = gg * (c + ig);        // faithful: forget gate unused
        float hn = og * tanh_(c);        // faithful: uses OLD cell state
        cbuf[b * HH + j] = cn;
        hdst[b * HH + j] = hn;
        if (LAYER == 1) out[((size_t)b * TT + t) * HH + j] = hn;
    }
}

__global__ void finalize(float* __restrict__ out) {
    int i = blockIdx.x * blockDim.x + threadIdx.x;
    if (i < NB * HH) {
        // after t = 255, last write parity = (255+1)&1 = 0
        out[(size_t)NB * TT * HH + i] = g_h1[0][i];
        out[(size_t)NB * TT * HH + NB * HH + i] = g_c1[i];
    }
}

extern "C" void kernel_launch(void* const* d_in, const int* in_sizes, int n_in,
                              void* d_out, int out_size) {
    const float* x   = (const float*)d_in[0];
    const float* Wx0 = (const float*)d_in[1];
    const float* Wh0 = (const float*)d_in[2];
    const float* b0  = (const float*)d_in[3];
    const float* Wc0 = (const float*)d_in[4];
    const float* Wx1 = (const float*)d_in[5];
    const float* Wh1 = (const float*)d_in[6];
    const float* b1  = (const float*)d_in[7];
    const float* Wc1 = (const float*)d_in[8];
    float* out = (float*)d_out;

    init_state<<<(NB * HH + 255) / 256, 256>>>();
    precompute_gx0<<<dim3(128, 48), 256>>>(x, Wx0, b0);
    for (int t = 0; t < TT; t++) {
        lstm_step<0><<<128, 128>>>(Wh0, nullptr, nullptr, Wc0, out, t);
        lstm_step<1><<<128, 128>>>(Wh1, Wx1, b1, Wc1, out, t);
    }
    finalize<<<(NB * HH + 255) / 256, 256>>>(out);
}

// round 2
// speedup vs baseline: 2.2069x; 2.2069x over previous
#include <cuda_runtime.h>
#include <math.h>

#define NB 64
#define TT 256
#define INDIM 512
#define HH 1024
#define G3 3072        // packed gate cols [i | g | o]; f gate skipped (unused in ref)
#define GRID 296
#define SPLITS 12
#define NSUB 288       // 24 col-tiles(128) * 12 K-splits
#define KC 32          // K elements per chunk/stage

// ---- static device scratch (no allocations allowed) ----
__device__ float g_gx0[(size_t)NB * TT * G3];   // precomputed x@Wx0^T + b0
__device__ float g_h0[NB * HH];
__device__ float g_h1[NB * HH];
__device__ float g_c0[NB * HH];
__device__ float g_c1[NB * HH];
__device__ float g_part0[(size_t)SPLITS * NB * G3];   // K-split partials, layer 0
__device__ float g_part1[(size_t)SPLITS * NB * G3];   // K-split partials, layer 1
__device__ unsigned g_bar;

__device__ __forceinline__ float sigmoid_(float x) { return 1.0f / (1.0f + expf(-x)); }
__device__ __forceinline__ float tanh_(float x) { return 1.0f - 2.0f / (expf(2.0f * x) + 1.0f); }

// monotonic-counter grid barrier (all GRID CTAs must be co-resident)
__device__ __forceinline__ void grid_sync(unsigned target) {
    __syncthreads();
    if (threadIdx.x == 0) {
        __threadfence();
        atomicAdd(&g_bar, 1u);
        unsigned v;
        do {
            asm volatile("ld.global.acquire.gpu.u32 %0, [%1];" : "=r"(v) : "l"(&g_bar));
        } while (v < target);
    }
    __syncthreads();
}

__global__ void init_state() {
    int i = blockIdx.x * blockDim.x + threadIdx.x;
    if (i == 0) g_bar = 0u;
    if (i < NB * HH) {
        g_h0[i] = 0.f; g_h1[i] = 0.f; g_c0[i] = 0.f; g_c1[i] = 0.f;
    }
}

// ---------------------------------------------------------------------------
// Precompute gx0[nt][jj] = b0 + x @ Wx0^T   (packed 3-gate cols), from R1.
// ---------------------------------------------------------------------------
__global__ __launch_bounds__(256) void precompute_gx0(
    const float* __restrict__ x, const float* __restrict__ Wx0,
    const float* __restrict__ b0)
{
    __shared__ float sx[128 * 17];
    __shared__ float sw[64 * 17];
    const int row0 = blockIdx.x * 128;
    const int col0 = blockIdx.y * 64;
    const int tid = threadIdx.x;
    const int ty = tid >> 4;
    const int tx = tid & 15;

    float acc[8][4];
#pragma unroll
    for (int i = 0; i < 8; i++)
#pragma unroll
        for (int j = 0; j < 4; j++) acc[i][j] = 0.f;

    for (int k0 = 0; k0 < INDIM; k0 += 16) {
#pragma unroll
        for (int it = 0; it < 2; it++) {
            int lin = tid + it * 256;
            int r = lin >> 2;
            int kq = (lin & 3) << 2;
            float4 v = *reinterpret_cast<const float4*>(
                &x[(size_t)(row0 + r) * INDIM + k0 + kq]);
            float* d = &sx[r * 17 + kq];
            d[0] = v.x; d[1] = v.y; d[2] = v.z; d[3] = v.w;
        }
#pragma unroll
        for (int it = 0; it < 4; it++) {
            int lin = tid + it * 256;
            int c = lin >> 4;
            int k = lin & 15;
            int jj = col0 + c;
            int wrow = jj + ((jj >= HH) ? HH : 0);
            sw[c * 17 + k] = Wx0[(size_t)wrow * INDIM + k0 + k];
        }
        __syncthreads();
#pragma unroll
        for (int kk = 0; kk < 16; kk++) {
            float xr[8], wr[4];
#pragma unroll
            for (int i = 0; i < 8; i++) xr[i] = sx[(ty * 8 + i) * 17 + kk];
#pragma unroll
            for (int j = 0; j < 4; j++) wr[j] = sw[(tx * 4 + j) * 17 + kk];
#pragma unroll
            for (int i = 0; i < 8; i++)
#pragma unroll
                for (int j = 0; j < 4; j++) acc[i][j] += xr[i] * wr[j];
        }
        __syncthreads();
    }
#pragma unroll
    for (int j = 0; j < 4; j++) {
        int jj = col0 + tx * 4 + j;
        int wrow = jj + ((jj >= HH) ? HH : 0);
        float bias = b0[wrow];
#pragma unroll
        for (int i = 0; i < 8; i++) {
            int r = row0 + ty * 8 + i;
            g_gx0[(size_t)r * G3 + jj] = acc[i][j] + bias;
        }
    }
}

// ---------------------------------------------------------------------------
// Persistent recurrent kernel: 256 steps x (GEMM L0 | pw L0 | GEMM L1 | pw L1)
// GEMM subtile: 64 batch x 128 cols, K-split over SPLITS chunks-of-KC.
// 256 threads, thread tile 8 batch x 4 cols. smem staged [k][b] / [k][col].
// ---------------------------------------------------------------------------
template <int LAYER>
__device__ __forceinline__ void gemm_phase(
    const float* __restrict__ Wh0, const float* __restrict__ Wx1,
    const float* __restrict__ Wh1, float* __restrict__ part,
    float* __restrict__ shb, float* __restrict__ swb)   // [2][KC*64], [2][KC*128]
{
    const int sid = blockIdx.x;
    if (sid >= NSUB) return;
    const int ct = sid / SPLITS;
    const int sp = sid - ct * SPLITS;
    const int col0 = ct * 128;
    const int growbase = col0 + (col0 >= HH ? HH : 0);
    const int CH = (LAYER == 0) ? 32 : 64;          // total KC-chunks
    const int lo = (sp * CH) / SPLITS;
    const int hi = ((sp + 1) * CH) / SPLITS;

    const int tid = threadIdx.x;
    const int ty = tid >> 5;    // 0..7  (8 batch rows each)
    const int tx = tid & 31;    // 0..31 (4 cols each)

    float acc[8][4];
#pragma unroll
    for (int i = 0; i < 8; i++)
#pragma unroll
        for (int j = 0; j < 4; j++) acc[i][j] = 0.f;

    float4 hreg[2], wreg[4];

    auto load_chunk = [&](int c) {
        const float* hp; const float* Wp; int k0;
        if (LAYER == 0)      { hp = g_h0; Wp = Wh0; k0 = c * KC; }
        else if (c < 32)     { hp = g_h0; Wp = Wx1; k0 = c * KC; }
        else                 { hp = g_h1; Wp = Wh1; k0 = (c - 32) * KC; }
#pragma unroll
        for (int i = 0; i < 2; i++) {
            int idx = tid + i * 256;
            hreg[i] = *reinterpret_cast<const float4*>(
                &hp[(idx & 63) * HH + k0 + ((idx >> 6) << 2)]);
        }
#pragma unroll
        for (int i = 0; i < 4; i++) {
            int idx = tid + i * 256;
            wreg[i] = *reinterpret_cast<const float4*>(
                &Wp[(size_t)(growbase + (idx & 127)) * HH + k0 + ((idx >> 7) << 2)]);
        }
    };
    auto store_chunk = [&](float* sh, float* sw) {
#pragma unroll
        for (int i = 0; i < 2; i++) {
            int idx = tid + i * 256;
            int kq = (idx >> 6) << 2;
            int b = idx & 63;
            sh[(kq + 0) * 64 + b] = hreg[i].x;
            sh[(kq + 1) * 64 + b] = hreg[i].y;
            sh[(kq + 2) * 64 + b] = hreg[i].z;
            sh[(kq + 3) * 64 + b] = hreg[i].w;
        }
#pragma unroll
        for (int i = 0; i < 4; i++) {
            int idx = tid + i * 256;
            int kq = (idx >> 7) << 2;
            int cc = idx & 127;
            sw[(kq + 0) * 128 + cc] = wreg[i].x;
            sw[(kq + 1) * 128 + cc] = wreg[i].y;
            sw[(kq + 2) * 128 + cc] = wreg[i].z;
            sw[(kq + 3) * 128 + cc] = wreg[i].w;
        }
    };

    load_chunk(lo);
    store_chunk(shb, swb);
    __syncthreads();

    for (int c = lo; c < hi; c++) {
        const int buf = (c - lo) & 1;
        if (c + 1 < hi) load_chunk(c + 1);
        const float* sh = shb + buf * (KC * 64);
        const float* sw = swb + buf * (KC * 128);
#pragma unroll
        for (int kk = 0; kk < KC; kk++) {
            float4 ha = *reinterpret_cast<const float4*>(&sh[kk * 64 + (ty << 3)]);
            float4 hb = *reinterpret_cast<const float4*>(&sh[kk * 64 + (ty << 3) + 4]);
            float4 wv = *reinterpret_cast<const float4*>(&sw[kk * 128 + (tx << 2)]);
            float hv[8] = {ha.x, ha.y, ha.z, ha.w, hb.x, hb.y, hb.z, hb.w};
            float wr[4] = {wv.x, wv.y, wv.z, wv.w};
#pragma unroll
            for (int i = 0; i < 8; i++)
#pragma unroll
                for (int j = 0; j < 4; j++) acc[i][j] += hv[i] * wr[j];
        }
        if (c + 1 < hi) {
            store_chunk(shb + (buf ^ 1) * (KC * 64), swb + (buf ^ 1) * (KC * 128));
            __syncthreads();
        }
    }

    float* pb = part + (size_t)sp * (NB * G3) + col0 + (tx << 2);
#pragma unroll
    for (int i = 0; i < 8; i++) {
        int b = (ty << 3) + i;
        *reinterpret_cast<float4*>(&pb[(size_t)b * G3]) =
            make_float4(acc[i][0], acc[i][1], acc[i][2], acc[i][3]);
    }
}

template <int LAYER>
__device__ __forceinline__ void pointwise(
    const float* __restrict__ part, const float* __restrict__ bias,
    const float* __restrict__ Wc, float* __restrict__ out, int t)
{
    const int cell = blockIdx.x * 256 + threadIdx.x;
    if (cell >= NB * HH) return;
    const int b = cell >> 10;
    const int j = cell & 1023;

    float si = 0.f, sg = 0.f, so = 0.f;
#pragma unroll
    for (int sp = 0; sp < SPLITS; sp++) {
        const float* p = part + (size_t)sp * (NB * G3) + (size_t)b * G3 + j;
        si += p[0];
        sg += p[HH];
        so += p[2 * HH];
    }
    float pre_i, pre_g, pre_o;
    if (LAYER == 0) {
        const float* gx = &g_gx0[((size_t)b * TT + t) * G3 + j];
        pre_i = si + gx[0];
        pre_g = sg + gx[HH];
        pre_o = so + gx[2 * HH];
    } else {
        pre_i = si + bias[j];
        pre_g = sg + bias[2 * HH + j];
        pre_o = so + bias[3 * HH + j];
    }
    float* cb = (LAYER == 0) ? g_c0 : g_c1;
    float c = cb[cell];
    float ig = sigmoid_(pre_i + Wc[j] * c);
    float gg = tanh_(pre_g);
    float og = sigmoid_(pre_o + Wc[2 * HH + j] * c);
    float cn = gg * (c + ig);      // faithful: forget gate unused
    float hn = og * tanh_(c);      // faithful: uses OLD cell state
    cb[cell] = cn;
    if (LAYER == 0) {
        g_h0[cell] = hn;
    } else {
        g_h1[cell] = hn;
        out[((size_t)b * TT + t) * HH + j] = hn;
        if (t == TT - 1) {
            out[(size_t)NB * TT * HH + cell] = hn;
            out[(size_t)NB * TT * HH + NB * HH + cell] = cn;
        }
    }
}

__global__ __launch_bounds__(256, 2) void lstm_persistent(
    const float* __restrict__ Wh0, const float* __restrict__ Wx1,
    const float* __restrict__ Wh1, const float* __restrict__ b1,
    const float* __restrict__ Wc0, const float* __restrict__ Wc1,
    float* __restrict__ out)
{
    __shared__ float shb[2 * KC * 64];    // 16 KB
    __shared__ float swb[2 * KC * 128];   // 32 KB  (total 48 KB/CTA)

    unsigned gen = 0;
    for (int t = 0; t < TT; t++) {
        gemm_phase<0>(Wh0, Wx1, Wh1, g_part0, shb, swb);
        grid_sync(++gen * GRID);
        pointwise<0>(g_part0, nullptr, Wc0, out, t);
        grid_sync(++gen * GRID);
        gemm_phase<1>(Wh0, Wx1, Wh1, g_part1, shb, swb);
        grid_sync(++gen * GRID);
        pointwise<1>(g_part1, b1, Wc1, out, t);
        // no sync: next gemm<0> touches only h0/part0, disjoint from pw<1>;
        // the sync after gemm<0>(t+1) fences pw<1>(t) before gemm<1>(t+1).
    }
}

extern "C" void kernel_launch(void* const* d_in, const int* in_sizes, int n_in,
                              void* d_out, int out_size) {
    const float* x   = (const float*)d_in[0];
    const float* Wx0 = (const float*)d_in[1];
    const float* Wh0 = (const float*)d_in[2];
    const float* b0  = (const float*)d_in[3];
    const float* Wc0 = (const float*)d_in[4];
    const float* Wx1 = (const float*)d_in[5];
    const float* Wh1 = (const float*)d_in[6];
    const float* b1  = (const float*)d_in[7];
    const float* Wc1 = (const float*)d_in[8];
    float* out = (float*)d_out;

    init_state<<<(NB * HH + 255) / 256, 256>>>();
    precompute_gx0<<<dim3(128, 48), 256>>>(x, Wx0, b0);
    lstm_persistent<<<GRID, 256>>>(Wh0, Wx1, Wh1, b1, Wc0, Wc1, out);
}

// round 3
// speedup vs baseline: 2.3178x; 1.0502x over previous
#include <cuda_runtime.h>
#include <math.h>

#define NB 64
#define TT 256
#define INDIM 512
#define HH 1024
#define G3 3072        // packed gate cols [i | g | o]; f gate skipped (unused in ref)
#define GRID 296
#define SPLITS 12
#define NSUB 288       // 24 col-tiles(128) * 12 K-splits
#define KC 32          // K elements per chunk/stage

// ---- static device scratch (no allocations allowed) ----
__device__ float g_gx0[(size_t)NB * TT * G3];   // precomputed x@Wx0^T + b0
__device__ float g_h0[NB * HH];
__device__ float g_h1[NB * HH];
__device__ float g_c0[NB * HH];
__device__ float g_c1[NB * HH];
__device__ float g_part0[(size_t)SPLITS * NB * G3];   // K-split partials, layer 0
__device__ float g_part1[(size_t)SPLITS * NB * G3];   // K-split partials, layer 1
__device__ unsigned g_bar;

__device__ __forceinline__ float sigmoid_(float x) { return 1.0f / (1.0f + expf(-x)); }
__device__ __forceinline__ float tanh_(float x) { return 1.0f - 2.0f / (expf(2.0f * x) + 1.0f); }

// monotonic-counter grid barrier (all GRID CTAs must be co-resident)
__device__ __forceinline__ void grid_sync(unsigned target) {
    __syncthreads();
    if (threadIdx.x == 0) {
        __threadfence();
        atomicAdd(&g_bar, 1u);
        unsigned v;
        do {
            asm volatile("ld.global.acquire.gpu.u32 %0, [%1];" : "=r"(v) : "l"(&g_bar));
        } while (v < target);
    }
    __syncthreads();
}

__global__ void init_state() {
    int i = blockIdx.x * blockDim.x + threadIdx.x;
    if (i == 0) g_bar = 0u;
    if (i < NB * HH) {
        g_h0[i] = 0.f; g_h1[i] = 0.f; g_c0[i] = 0.f; g_c1[i] = 0.f;
    }
}

// ---------------------------------------------------------------------------
// Precompute gx0[nt][jj] = b0 + x @ Wx0^T   (packed 3-gate cols), from R1.
// ---------------------------------------------------------------------------
__global__ __launch_bounds__(256) void precompute_gx0(
    const float* __restrict__ x, const float* __restrict__ Wx0,
    const float* __restrict__ b0)
{
    __shared__ float sx[128 * 17];
    __shared__ float sw[64 * 17];
    const int row0 = blockIdx.x * 128;
    const int col0 = blockIdx.y * 64;
    const int tid = threadIdx.x;
    const int ty = tid >> 4;
    const int tx = tid & 15;

    float acc[8][4];
#pragma unroll
    for (int i = 0; i < 8; i++)
#pragma unroll
        for (int j = 0; j < 4; j++) acc[i][j] = 0.f;

    for (int k0 = 0; k0 < INDIM; k0 += 16) {
#pragma unroll
        for (int it = 0; it < 2; it++) {
            int lin = tid + it * 256;
            int r = lin >> 2;
            int kq = (lin & 3) << 2;
            float4 v = *reinterpret_cast<const float4*>(
                &x[(size_t)(row0 + r) * INDIM + k0 + kq]);
            float* d = &sx[r * 17 + kq];
            d[0] = v.x; d[1] = v.y; d[2] = v.z; d[3] = v.w;
        }
#pragma unroll
        for (int it = 0; it < 4; it++) {
            int lin = tid + it * 256;
            int c = lin >> 4;
            int k = lin & 15;
            int jj = col0 + c;
            int wrow = jj + ((jj >= HH) ? HH : 0);
            sw[c * 17 + k] = Wx0[(size_t)wrow * INDIM + k0 + k];
        }
        __syncthreads();
#pragma unroll
        for (int kk = 0; kk < 16; kk++) {
            float xr[8], wr[4];
#pragma unroll
            for (int i = 0; i < 8; i++) xr[i] = sx[(ty * 8 + i) * 17 + kk];
#pragma unroll
            for (int j = 0; j < 4; j++) wr[j] = sw[(tx * 4 + j) * 17 + kk];
#pragma unroll
            for (int i = 0; i < 8; i++)
#pragma unroll
                for (int j = 0; j < 4; j++) acc[i][j] += xr[i] * wr[j];
        }
        __syncthreads();
    }
#pragma unroll
    for (int j = 0; j < 4; j++) {
        int jj = col0 + tx * 4 + j;
        int wrow = jj + ((jj >= HH) ? HH : 0);
        float bias = b0[wrow];
#pragma unroll
        for (int i = 0; i < 8; i++) {
            int r = row0 + ty * 8 + i;
            g_gx0[(size_t)r * G3 + jj] = acc[i][j] + bias;
        }
    }
}

// ---------------------------------------------------------------------------
// Persistent recurrent kernel: 256 steps x (GEMM L0 | pw L0 | GEMM L1 | pw L1)
// GEMM subtile: 64 batch x 128 cols, K-split over SPLITS chunks-of-KC.
// 256 threads, thread tile 8 batch x 4 cols. smem staged [k][b] / [k][col].
// ---------------------------------------------------------------------------
template <int LAYER>
__device__ __forceinline__ void gemm_phase(
    const float* __restrict__ Wh0, const float* __restrict__ Wx1,
    const float* __restrict__ Wh1, float* __restrict__ part,
    float* __restrict__ shb, float* __restrict__ swb)   // [2][KC*64], [2][KC*128]
{
    const int sid = blockIdx.x;
    if (sid >= NSUB) return;
    const int ct = sid / SPLITS;
    const int sp = sid - ct * SPLITS;
    const int col0 = ct * 128;
    const int growbase = col0 + (col0 >= HH ? HH : 0);
    const int CH = (LAYER == 0) ? 32 : 64;          // total KC-chunks
    const int lo = (sp * CH) / SPLITS;
    const int hi = ((sp + 1) * CH) / SPLITS;

    const int tid = threadIdx.x;
    const int ty = tid >> 5;    // 0..7  (8 batch rows each)
    const int tx = tid & 31;    // 0..31 (4 cols each)

    float acc[8][4];
#pragma unroll
    for (int i = 0; i < 8; i++)
#pragma unroll
        for (int j = 0; j < 4; j++) acc[i][j] = 0.f;

    float4 hreg[2], wreg[4];

    auto load_chunk = [&](int c) {
        const float* hp; const float* Wp; int k0;
        if (LAYER == 0)      { hp = g_h0; Wp = Wh0; k0 = c * KC; }
        else if (c < 32)     { hp = g_h0; Wp = Wx1; k0 = c * KC; }
        else                 { hp = g_h1; Wp = Wh1; k0 = (c - 32) * KC; }
#pragma unroll
        for (int i = 0; i < 2; i++) {
            int idx = tid + i * 256;
            hreg[i] = *reinterpret_cast<const float4*>(
                &hp[(idx & 63) * HH + k0 + ((idx >> 6) << 2)]);
        }
#pragma unroll
        for (int i = 0; i < 4; i++) {
            int idx = tid + i * 256;
            wreg[i] = *reinterpret_cast<const float4*>(
                &Wp[(size_t)(growbase + (idx & 127)) * HH + k0 + ((idx >> 7) << 2)]);
        }
    };
    auto store_chunk = [&](float* sh, float* sw) {
#pragma unroll
        for (int i = 0; i < 2; i++) {
            int idx = tid + i * 256;
            int kq = (idx >> 6) << 2;
            int b = idx & 63;
            sh[(kq + 0) * 64 + b] = hreg[i].x;
            sh[(kq + 1) * 64 + b] = hreg[i].y;
            sh[(kq + 2) * 64 + b] = hreg[i].z;
            sh[(kq + 3) * 64 + b] = hreg[i].w;
        }
#pragma unroll
        for (int i = 0; i < 4; i++) {
            int idx = tid + i * 256;
            int kq = (idx >> 7) << 2;
            int cc = idx & 127;
            sw[(kq + 0) * 128 + cc] = wreg[i].x;
            sw[(kq + 1) * 128 + cc] = wreg[i].y;
            sw[(kq + 2) * 128 + cc] = wreg[i].z;
            sw[(kq + 3) * 128 + cc] = wreg[i].w;
        }
    };

    load_chunk(lo);
    store_chunk(shb, swb);
    __syncthreads();

    for (int c = lo; c < hi; c++) {
        const int buf = (c - lo) & 1;
        if (c + 1 < hi) load_chunk(c + 1);
        const float* sh = shb + buf * (KC * 64);
        const float* sw = swb + buf * (KC * 128);
#pragma unroll
        for (int kk = 0; kk < KC; kk++) {
            float4 ha = *reinterpret_cast<const float4*>(&sh[kk * 64 + (ty << 3)]);
            float4 hb = *reinterpret_cast<const float4*>(&sh[kk * 64 + (ty << 3) + 4]);
            float4 wv = *reinterpret_cast<const float4*>(&sw[kk * 128 + (tx << 2)]);
            float hv[8] = {ha.x, ha.y, ha.z, ha.w, hb.x, hb.y, hb.z, hb.w};
            float wr[4] = {wv.x, wv.y, wv.z, wv.w};
#pragma unroll
            for (int i = 0; i < 8; i++)
#pragma unroll
                for (int j = 0; j < 4; j++) acc[i][j] += hv[i] * wr[j];
        }
        if (c + 1 < hi) {
            store_chunk(shb + (buf ^ 1) * (KC * 64), swb + (buf ^ 1) * (KC * 128));
            __syncthreads();
        }
    }

    float* pb = part + (size_t)sp * (NB * G3) + col0 + (tx << 2);
#pragma unroll
    for (int i = 0; i < 8; i++) {
        int b = (ty << 3) + i;
        *reinterpret_cast<float4*>(&pb[(size_t)b * G3]) =
            make_float4(acc[i][0], acc[i][1], acc[i][2], acc[i][3]);
    }
}

template <int LAYER>
__device__ __forceinline__ void pointwise(
    const float* __restrict__ part, const float* __restrict__ bias,
    const float* __restrict__ Wc, float* __restrict__ out, int t)
{
    const int cell = blockIdx.x * 256 + threadIdx.x;
    if (cell >= NB * HH) return;
    const int b = cell >> 10;
    const int j = cell & 1023;

    float si = 0.f, sg = 0.f, so = 0.f;
#pragma unroll
    for (int sp = 0; sp < SPLITS; sp++) {
        const float* p = part + (size_t)sp * (NB * G3) + (size_t)b * G3 + j;
        si += p[0];
        sg += p[HH];
        so += p[2 * HH];
    }
    float pre_i, pre_g, pre_o;
    if (LAYER == 0) {
        const float* gx = &g_gx0[((size_t)b * TT + t) * G3 + j];
        pre_i = si + gx[0];
        pre_g = sg + gx[HH];
        pre_o = so + gx[2 * HH];
    } else {
        pre_i = si + bias[j];
        pre_g = sg + bias[2 * HH + j];
        pre_o = so + bias[3 * HH + j];
    }
    float* cb = (LAYER == 0) ? g_c0 : g_c1;
    float c = cb[cell];
    float ig = sigmoid_(pre_i + Wc[j] * c);
    float gg = tanh_(pre_g);
    float og = sigmoid_(pre_o + Wc[2 * HH + j] * c);
    float cn = gg * (c + ig);      // faithful: forget gate unused
    float hn = og * tanh_(c);      // faithful: uses OLD cell state
    cb[cell] = cn;
    if (LAYER == 0) {
        g_h0[cell] = hn;
    } else {
        g_h1[cell] = hn;
        out[((size_t)b * TT + t) * HH + j] = hn;
        if (t == TT - 1) {
            out[(size_t)NB * TT * HH + cell] = hn;
            out[(size_t)NB * TT * HH + NB * HH + cell] = cn;
        }
    }
}

__global__ __launch_bounds__(256, 2) void lstm_persistent(
    const float* __restrict__ Wh0, const float* __restrict__ Wx1,
    const float* __restrict__ Wh1, const float* __restrict__ b1,
    const float* __restrict__ Wc0, const float* __restrict__ Wc1,
    float* __restrict__ out)
{
    __shared__ float shb[2 * KC * 64];    // 16 KB
    __shared__ float swb[2 * KC * 128];   // 32 KB  (total 48 KB/CTA)

    unsigned gen = 0;
    for (int t = 0; t < TT; t++) {
        gemm_phase<0>(Wh0, Wx1, Wh1, g_part0, shb, swb);
        grid_sync(++gen * GRID);
        pointwise<0>(g_part0, nullptr, Wc0, out, t);
        grid_sync(++gen * GRID);
        gemm_phase<1>(Wh0, Wx1, Wh1, g_part1, shb, swb);
        grid_sync(++gen * GRID);
        pointwise<1>(g_part1, b1, Wc1, out, t);
        // no sync: next gemm<0> touches only h0/part0, disjoint from pw<1>;
        // the sync after gemm<0>(t+1) fences pw<1>(t) before gemm<1>(t+1).
    }
}

extern "C" void kernel_launch(void* const* d_in, const int* in_sizes, int n_in,
                              void* d_out, int out_size) {
    const float* x   = (const float*)d_in[0];
    const float* Wx0 = (const float*)d_in[1];
    const float* Wh0 = (const float*)d_in[2];
    const float* b0  = (const float*)d_in[3];
    const float* Wc0 = (const float*)d_in[4];
    const float* Wx1 = (const float*)d_in[5];
    const float* Wh1 = (const float*)d_in[6];
    const float* b1  = (const float*)d_in[7];
    const float* Wc1 = (const float*)d_in[8];
    float* out = (float*)d_out;

    init_state<<<(NB * HH + 255) / 256, 256>>>();
    precompute_gx0<<<dim3(128, 48), 256>>>(x, Wx0, b0);
    lstm_persistent<<<GRID, 256>>>(Wh0, Wx1, Wh1, b1, Wc0, Wc1, out);
}

// round 5
// speedup vs baseline: 5.5123x; 2.3783x over previous
#include <cuda_runtime.h>
#include <cuda_bf16.h>
#include <math.h>
#include <stdint.h>

#define NB 64
#define TT 256
#define INDIM 512
#define HH 1024
#define G3 3072
#define GRID 144
#define SPLITS 6
#define STAGE_BYTES 49152
#define OFF_WH 0
#define OFF_WL 16384
#define OFF_BH 32768
#define OFF_BL 40960
#define SMEM_TOTAL (3 * STAGE_BYTES)

// ---------------- static device scratch ----------------
__device__ float g_gx0[(size_t)NB * TT * G3];
__device__ float g_c0[NB * HH];
__device__ float g_c1[NB * HH];
__device__ float g_part0[(size_t)SPLITS * NB * G3];
__device__ float g_part1[(size_t)SPLITS * NB * G3];
__device__ unsigned g_bar;

__device__ __align__(16) __nv_bfloat16 g_h0h[NB * HH];
__device__ __align__(16) __nv_bfloat16 g_h0l[NB * HH];
__device__ __align__(16) __nv_bfloat16 g_h1h[NB * HH];
__device__ __align__(16) __nv_bfloat16 g_h1l[NB * HH];
__device__ __align__(16) __nv_bfloat16 g_xh[(size_t)NB * TT * INDIM];
__device__ __align__(16) __nv_bfloat16 g_xl[(size_t)NB * TT * INDIM];
__device__ __align__(16) __nv_bfloat16 g_Wx0h[(size_t)G3 * INDIM];
__device__ __align__(16) __nv_bfloat16 g_Wx0l[(size_t)G3 * INDIM];
__device__ __align__(16) __nv_bfloat16 g_Wh0h[(size_t)G3 * HH];
__device__ __align__(16) __nv_bfloat16 g_Wh0l[(size_t)G3 * HH];
__device__ __align__(16) __nv_bfloat16 g_Wx1h[(size_t)G3 * HH];
__device__ __align__(16) __nv_bfloat16 g_Wx1l[(size_t)G3 * HH];
__device__ __align__(16) __nv_bfloat16 g_Wh1h[(size_t)G3 * HH];
__device__ __align__(16) __nv_bfloat16 g_Wh1l[(size_t)G3 * HH];

// ---------------- helpers ----------------
__device__ __forceinline__ float sigmoid_(float x) { return 1.0f / (1.0f + expf(-x)); }
__device__ __forceinline__ float tanh_(float x) { return 1.0f - 2.0f / (expf(2.0f * x) + 1.0f); }

__device__ __forceinline__ uint32_t smem_u32(const void* p) {
    uint32_t a;
    asm("{ .reg .u64 t; cvta.to.shared.u64 t, %1; cvt.u32.u64 %0, t; }" : "=r"(a) : "l"(p));
    return a;
}
#define SWZ(x) ((x) ^ (((x) >> 3) & 0x70))

__device__ __forceinline__ void cp16(uint32_t dst, const void* src) {
    asm volatile("cp.async.cg.shared.global [%0], [%1], 16;" :: "r"(dst), "l"(src));
}

#define LDSM4(r, addr) \
    asm volatile("ldmatrix.sync.aligned.m8n8.x4.shared.b16 {%0,%1,%2,%3}, [%4];" \
        : "=r"((r)[0]), "=r"((r)[1]), "=r"((r)[2]), "=r"((r)[3]) : "r"(addr))

#define MMA(c, a, b0, b1) \
    asm volatile("mma.sync.aligned.m16n8k16.row.col.f32.bf16.bf16.f32 " \
        "{%0,%1,%2,%3},{%4,%5,%6,%7},{%8,%9},{%0,%1,%2,%3};" \
        : "+f"((c)[0]), "+f"((c)[1]), "+f"((c)[2]), "+f"((c)[3]) \
        : "r"((a)[0]), "r"((a)[1]), "r"((a)[2]), "r"((a)[3]), "r"(b0), "r"(b1))

__device__ __forceinline__ void grid_sync(unsigned target) {
    __threadfence();
    __syncthreads();
    if (threadIdx.x == 0) {
        atomicAdd(&g_bar, 1u);
        unsigned v;
        do {
            asm volatile("ld.global.acquire.gpu.u32 %0, [%1];" : "=r"(v) : "l"(&g_bar));
        } while (v < target);
    }
    __syncthreads();
}

// ---------------- init / convert ----------------
__global__ void init_state() {
    int i = blockIdx.x * blockDim.x + threadIdx.x;
    if (i == 0) g_bar = 0u;
    if (i < NB * HH) {
        g_c0[i] = 0.f; g_c1[i] = 0.f;
        __nv_bfloat16 z = __float2bfloat16(0.f);
        g_h0h[i] = z; g_h0l[i] = z; g_h1h[i] = z; g_h1l[i] = z;
    }
}

#define NW0 ((size_t)G3 * INDIM)
#define NW1 ((size_t)G3 * HH)
#define NX  ((size_t)NB * TT * INDIM)

__global__ void convert_all(const float* __restrict__ x,
    const float* __restrict__ Wx0, const float* __restrict__ Wh0,
    const float* __restrict__ Wx1, const float* __restrict__ Wh1)
{
    size_t idx = (size_t)blockIdx.x * 256 + threadIdx.x;
    float v; __nv_bfloat16 *dh, *dl; size_t o;
    if (idx < NW0) {
        int r = (int)(idx / INDIM), k = (int)(idx % INDIM);
        int orig = r + (r >= HH ? HH : 0);     // skip f-gate rows
        v = Wx0[(size_t)orig * INDIM + k];
        dh = g_Wx0h; dl = g_Wx0l; o = idx;
    } else if (idx < NW0 + 3 * NW1) {
        size_t i2 = idx - NW0;
        int mat = (int)(i2 / NW1);
        size_t i3 = i2 % NW1;
        int r = (int)(i3 / HH), k = (int)(i3 % HH);
        int orig = r + (r >= HH ? HH : 0);
        const float* W = mat == 0 ? Wh0 : (mat == 1 ? Wx1 : Wh1);
        v = W[(size_t)orig * HH + k];
        dh = mat == 0 ? g_Wh0h : (mat == 1 ? g_Wx1h : g_Wh1h);
        dl = mat == 0 ? g_Wh0l : (mat == 1 ? g_Wx1l : g_Wh1l);
        o = i3;
    } else {
        size_t i2 = idx - NW0 - 3 * NW1;
        if (i2 >= NX) return;
        v = x[i2]; dh = g_xh; dl = g_xl; o = i2;
    }
    __nv_bfloat16 h = __float2bfloat16(v);
    dh[o] = h;
    dl[o] = __float2bfloat16(v - __bfloat162float(h));
}

// ---------------- GEMM tile engine ----------------
// Stage: W 128 rows x 64 bf16 (hi+lo), B 64 rows x 64 bf16 (hi+lo), SW128 swizzled.
__device__ __forceinline__ void load_chunk_cp(
    uint32_t sbase,
    const __nv_bfloat16* __restrict__ Wh, const __nv_bfloat16* __restrict__ Wl,
    const __nv_bfloat16* __restrict__ Bh, const __nv_bfloat16* __restrict__ Bl,
    int k0, int ws, int bs, int tid)
{
#pragma unroll
    for (int i = 0; i < 4; i++) {
        int seg = tid + i * 256;
        int row = seg >> 3, sc = seg & 7;
        uint32_t so = SWZ((uint32_t)(row * 128 + sc * 16));
        size_t off = (size_t)row * ws + k0 + sc * 8;
        cp16(sbase + OFF_WH + so, Wh + off);
        cp16(sbase + OFF_WL + so, Wl + off);
    }
#pragma unroll
    for (int i = 0; i < 2; i++) {
        int seg = tid + i * 256;
        int row = seg >> 3, sc = seg & 7;
        uint32_t so = SWZ((uint32_t)(row * 128 + sc * 16));
        size_t off = (size_t)row * bs + k0 + sc * 8;
        cp16(sbase + OFF_BH + so, Bh + off);
        cp16(sbase + OFF_BL + so, Bl + off);
    }
    asm volatile("cp.async.commit_group;" ::: "memory");
}

__device__ __forceinline__ void compute_chunk(uint32_t stage, float acc[2][4][4],
                                              int lane, int warpM, int warpN)
{
#pragma unroll
    for (int kk = 0; kk < 4; kk++) {
        const int kByte = kk * 32;
        uint32_t ah[2][4], al[2][4];
#pragma unroll
        for (int mt = 0; mt < 2; mt++) {
            int row = warpM * 32 + mt * 16 + (lane & 7) + ((lane >> 3) & 1) * 8;
            int col = kByte + ((lane >> 4) << 4);
            uint32_t a = SWZ((uint32_t)(row * 128 + col));
            LDSM4(ah[mt], stage + OFF_WH + a);
            LDSM4(al[mt], stage + OFF_WL + a);
        }
        uint32_t bh[2][4], bl[2][4];
#pragma unroll
        for (int p = 0; p < 2; p++) {
            int row = warpN * 32 + p * 16 + (lane & 7) + ((lane >> 4) & 1) * 8;
            int col = kByte + (((lane >> 3) & 1) << 4);
            uint32_t a = SWZ((uint32_t)(row * 128 + col));
            LDSM4(bh[p], stage + OFF_BH + a);
            LDSM4(bl[p], stage + OFF_BL + a);
        }
#pragma unroll
        for (int mt = 0; mt < 2; mt++)
#pragma unroll
            for (int nt = 0; nt < 4; nt++) {
                int p = nt >> 1, hf = nt & 1;
                MMA(acc[mt][nt], ah[mt], bh[p][hf * 2], bh[p][hf * 2 + 1]);
                MMA(acc[mt][nt], ah[mt], bl[p][hf * 2], bl[p][hf * 2 + 1]);
                MMA(acc[mt][nt], al[mt], bh[p][hf * 2], bh[p][hf * 2 + 1]);
            }
    }
}

template <typename F>
__device__ __forceinline__ void gemm_tile(uint32_t tiles, int lo, int NC,
                                          F&& get, float acc[2][4][4])
{
    const int tid = threadIdx.x;
    const int lane = tid & 31, wid = tid >> 5;
    const int warpM = wid & 3, warpN = wid >> 2;

    auto ld = [&](int c) {
        const __nv_bfloat16 *Wh, *Wl, *Bh, *Bl; int k0, ws, bs;
        get(lo + c, Wh, Wl, Bh, Bl, k0, ws, bs);
        load_chunk_cp(tiles + (c % 3) * STAGE_BYTES, Wh, Wl, Bh, Bl, k0, ws, bs, tid);
    };
    ld(0);
    if (NC > 1) ld(1);
    for (int c = 0; c < NC; c++) {
        if (c + 2 < NC) {
            ld(c + 2);
            asm volatile("cp.async.wait_group 2;" ::: "memory");
        } else if (c + 1 < NC) {
            asm volatile("cp.async.wait_group 1;" ::: "memory");
        } else {
            asm volatile("cp.async.wait_group 0;" ::: "memory");
        }
        __syncthreads();
        compute_chunk(tiles + (c % 3) * STAGE_BYTES, acc, lane, warpM, warpN);
        __syncthreads();
    }
}

// ---------------- precompute gx0 (tensor cores) ----------------
__global__ __launch_bounds__(256, 1) void precompute_tc(const float* __restrict__ b0) {
    extern __shared__ char smem[];
    uint32_t tiles = smem_u32(smem);
    const int ct = blockIdx.x % 24;
    const int nt0 = (blockIdx.x / 24) * 64;
    const int col0 = ct * 128;

    float acc[2][4][4];
#pragma unroll
    for (int i = 0; i < 2; i++)
#pragma unroll
        for (int j = 0; j < 4; j++)
#pragma unroll
            for (int k = 0; k < 4; k++) acc[i][j][k] = 0.f;

    auto get = [&](int c, const __nv_bfloat16*& Wh, const __nv_bfloat16*& Wl,
                   const __nv_bfloat16*& Bh, const __nv_bfloat16*& Bl,
                   int& k0, int& ws, int& bs) {
        ws = INDIM; bs = INDIM; k0 = c * 64;
        Wh = g_Wx0h + (size_t)col0 * INDIM;
        Wl = g_Wx0l + (size_t)col0 * INDIM;
        Bh = g_xh + (size_t)nt0 * INDIM;
        Bl = g_xl + (size_t)nt0 * INDIM;
    };
    gemm_tile(tiles, 0, INDIM / 64, get, acc);

    const int lane = threadIdx.x & 31, wid = threadIdx.x >> 5;
    const int warpM = wid & 3, warpN = wid >> 2;
    const int g = lane >> 2, tig = lane & 3;
#pragma unroll
    for (int mt = 0; mt < 2; mt++) {
        int colA = col0 + warpM * 32 + mt * 16 + g;
        float bias0 = b0[colA + (colA >= HH ? HH : 0)];
        float bias8 = b0[colA + 8 + (colA + 8 >= HH ? HH : 0)];
#pragma unroll
        for (int nt = 0; nt < 4; nt++) {
            int r = nt0 + warpN * 32 + nt * 8 + tig * 2;
            g_gx0[(size_t)r * G3 + colA] = acc[mt][nt][0] + bias0;
            g_gx0[(size_t)(r + 1) * G3 + colA] = acc[mt][nt][1] + bias0;
            g_gx0[(size_t)r * G3 + colA + 8] = acc[mt][nt][2] + bias8;
            g_gx0[(size_t)(r + 1) * G3 + colA + 8] = acc[mt][nt][3] + bias8;
        }
    }
}

// ---------------- recurrent persistent kernel ----------------
template <int LAYER>
__device__ __forceinline__ void gemm_phase(uint32_t tiles, float* __restrict__ part) {
    const int ct = blockIdx.x / SPLITS;
    const int sp = blockIdx.x % SPLITS;
    const int col0 = ct * 128;
    const int CH = (LAYER == 0) ? 16 : 32;
    const int lo = (sp * CH) / SPLITS;
    const int hi = ((sp + 1) * CH) / SPLITS;

    float acc[2][4][4];
#pragma unroll
    for (int i = 0; i < 2; i++)
#pragma unroll
        for (int j = 0; j < 4; j++)
#pragma unroll
            for (int k = 0; k < 4; k++) acc[i][j][k] = 0.f;

    auto get = [&](int c, const __nv_bfloat16*& Wh, const __nv_bfloat16*& Wl,
                   const __nv_bfloat16*& Bh, const __nv_bfloat16*& Bl,
                   int& k0, int& ws, int& bs) {
        ws = HH; bs = HH;
        if (LAYER == 0) {
            k0 = c * 64;
            Wh = g_Wh0h + (size_t)col0 * HH;
            Wl = g_Wh0l + (size_t)col0 * HH;
            Bh = g_h0h; Bl = g_h0l;
        } else {
            int kk = c * 64;
            if (kk < HH) {
                Wh = g_Wx1h + (size_t)col0 * HH;
                Wl = g_Wx1l + (size_t)col0 * HH;
                Bh = g_h0h; Bl = g_h0l; k0 = kk;
            } else {
                Wh = g_Wh1h + (size_t)col0 * HH;
                Wl = g_Wh1l + (size_t)col0 * HH;
                Bh = g_h1h; Bl = g_h1l; k0 = kk - HH;
            }
        }
    };
    gemm_tile(tiles, lo, hi - lo, get, acc);

    const int lane = threadIdx.x & 31, wid = threadIdx.x >> 5;
    const int warpM = wid & 3, warpN = wid >> 2;
    const int g = lane >> 2, tig = lane & 3;
#pragma unroll
    for (int mt = 0; mt < 2; mt++) {
        int colA = col0 + warpM * 32 + mt * 16 + g;
#pragma unroll
        for (int nt = 0; nt < 4; nt++) {
            int b = warpN * 32 + nt * 8 + tig * 2;
            float* p0 = part + ((size_t)sp * NB + b) * G3;
            p0[colA] = acc[mt][nt][0];
            p0[G3 + colA] = acc[mt][nt][1];
            p0[colA + 8] = acc[mt][nt][2];
            p0[G3 + colA + 8] = acc[mt][nt][3];
        }
    }
}

template <int LAYER>
__device__ __forceinline__ void pointwise(const float* __restrict__ part,
    const float* __restrict__ bias, const float* __restrict__ Wc,
    float* __restrict__ out, int t)
{
    for (int cell = blockIdx.x * 256 + threadIdx.x; cell < NB * HH; cell += GRID * 256) {
        int b = cell >> 10, j = cell & (HH - 1);
        float si = 0.f, sg = 0.f, so = 0.f;
#pragma unroll
        for (int sp = 0; sp < SPLITS; sp++) {
            const float* p = part + ((size_t)sp * NB + b) * G3 + j;
            si += p[0]; sg += p[HH]; so += p[2 * HH];
        }
        float pi, pg, po;
        if (LAYER == 0) {
            const float* gx = &g_gx0[((size_t)b * TT + t) * G3 + j];
            pi = si + gx[0]; pg = sg + gx[HH]; po = so + gx[2 * HH];
        } else {
            pi = si + bias[j]; pg = sg + bias[2 * HH + j]; po = so + bias[3 * HH + j];
        }
        float* cb = (LAYER == 0) ? g_c0 : g_c1;
        float c = cb[cell];
        float ig = sigmoid_(pi + Wc[j] * c);
        float gg = tanh_(pg);
        float og = sigmoid_(po + Wc[2 * HH + j] * c);
        float cn = gg * (c + ig);      // faithful: forget gate unused
        float hn = og * tanh_(c);      // faithful: uses OLD cell state
        cb[cell] = cn;
        __nv_bfloat16 hh = __float2bfloat16(hn);
        __nv_bfloat16 hl = __float2bfloat16(hn - __bfloat162float(hh));
        if (LAYER == 0) {
            g_h0h[cell] = hh; g_h0l[cell] = hl;
        } else {
            g_h1h[cell] = hh; g_h1l[cell] = hl;
            out[((size_t)b * TT + t) * HH + j] = hn;
            if (t == TT - 1) {
                out[(size_t)NB * TT * HH + cell] = hn;
                out[(size_t)NB * TT * HH + NB * HH + cell] = cn;
            }
        }
    }
}

__global__ __launch_bounds__(256, 1) void lstm_persistent(
    const float* __restrict__ b1, const float* __restrict__ Wc0,
    const float* __restrict__ Wc1, float* __restrict__ out)
{
    extern __shared__ char smem[];
    uint32_t tiles = smem_u32(smem);
    unsigned gen = 0;
    for (int t = 0; t < TT; t++) {
        gemm_phase<0>(tiles, g_part0);
        grid_sync(++gen * GRID);
        pointwise<0>(g_part0, nullptr, Wc0, out, t);
        grid_sync(++gen * GRID);
        gemm_phase<1>(tiles, g_part1);
        grid_sync(++gen * GRID);
        pointwise<1>(g_part1, b1, Wc1, out, t);
        // pw<1>(t) vs gemm<0>(t+1): disjoint buffers; the two syncs inside
        // step t+1 order pw<1>(t) before gemm<1>(t+1)'s h1/part1 accesses.
    }
}

// ---------------- host launch ----------------
extern "C" void kernel_launch(void* const* d_in, const int* in_sizes, int n_in,
                              void* d_out, int out_size) {
    const float* x   = (const float*)d_in[0];
    const float* Wx0 = (const float*)d_in[1];
    const float* Wh0 = (const float*)d_in[2];
    const float* b0  = (const float*)d_in[3];
    const float* Wc0 = (const float*)d_in[4];
    const float* Wx1 = (const float*)d_in[5];
    const float* Wh1 = (const float*)d_in[6];
    const float* b1  = (const float*)d_in[7];
    const float* Wc1 = (const float*)d_in[8];
    float* out = (float*)d_out;

    cudaFuncSetAttribute(precompute_tc,
                         cudaFuncAttributeMaxDynamicSharedMemorySize, SMEM_TOTAL);
    cudaFuncSetAttribute(lstm_persistent,
                         cudaFuncAttributeMaxDynamicSharedMemorySize, SMEM_TOTAL);

    size_t total_conv = NW0 + 3 * NW1 + NX;
    int conv_blocks = (int)((total_conv + 255) / 256);

    init_state<<<256, 256>>>();
    convert_all<<<conv_blocks, 256>>>(x, Wx0, Wh0, Wx1, Wh1);
    precompute_tc<<<24 * (NB * TT / 64), 256, SMEM_TOTAL>>>(b0);
    lstm_persistent<<<GRID, 256, SMEM_TOTAL>>>(b1, Wc0, Wc1, out);
}

// round 6
// speedup vs baseline: 5.8421x; 1.0598x over previous
#include <cuda_runtime.h>
#include <cuda_bf16.h>
#include <math.h>
#include <stdint.h>

#define NB 64
#define TT 256
#define INDIM 512
#define HH 1024
#define G3 3072
#define GRID 144
#define SPLITS 6
#define NTHREADS 512
#define STAGE_BYTES 49152
#define OFF_WH 0
#define OFF_WL 16384
#define OFF_BH 32768
#define OFF_BL 40960
#define SMEM_TOTAL (3 * STAGE_BYTES)

typedef __nv_bfloat16 bf16;

// ---------------- static device scratch ----------------
__device__ float g_gx0[(size_t)NB * TT * G3];
__device__ float g_c0[NB * HH];
__device__ float g_c1[NB * HH];
__device__ float g_part0[(size_t)SPLITS * NB * G3];
__device__ float g_part1[(size_t)SPLITS * NB * G3];
__device__ unsigned g_bar;

__device__ __align__(16) bf16 g_h0h[NB * HH];
__device__ __align__(16) bf16 g_h0l[NB * HH];
__device__ __align__(16) bf16 g_h1h[NB * HH];
__device__ __align__(16) bf16 g_h1l[NB * HH];
__device__ __align__(16) bf16 g_xh[(size_t)NB * TT * INDIM];
__device__ __align__(16) bf16 g_xl[(size_t)NB * TT * INDIM];
__device__ __align__(16) bf16 g_Wx0h[(size_t)G3 * INDIM];
__device__ __align__(16) bf16 g_Wx0l[(size_t)G3 * INDIM];
__device__ __align__(16) bf16 g_Wh0h[(size_t)G3 * HH];
__device__ __align__(16) bf16 g_Wh0l[(size_t)G3 * HH];
__device__ __align__(16) bf16 g_Wx1h[(size_t)G3 * HH];
__device__ __align__(16) bf16 g_Wx1l[(size_t)G3 * HH];
__device__ __align__(16) bf16 g_Wh1h[(size_t)G3 * HH];
__device__ __align__(16) bf16 g_Wh1l[(size_t)G3 * HH];

// ---------------- helpers ----------------
__device__ __forceinline__ float sigmoid_(float x) { return 1.0f / (1.0f + expf(-x)); }
__device__ __forceinline__ float tanh_(float x) { return 1.0f - 2.0f / (expf(2.0f * x) + 1.0f); }

__device__ __forceinline__ uint32_t smem_u32(const void* p) {
    uint32_t a;
    asm("{ .reg .u64 t; cvta.to.shared.u64 t, %1; cvt.u32.u64 %0, t; }" : "=r"(a) : "l"(p));
    return a;
}
#define SWZ(x) ((x) ^ (((x) >> 3) & 0x70))

__device__ __forceinline__ void cp16(uint32_t dst, const void* src) {
    asm volatile("cp.async.cg.shared.global [%0], [%1], 16;" :: "r"(dst), "l"(src));
}
#define CP_COMMIT() asm volatile("cp.async.commit_group;" ::: "memory")

#define LDSM4(r, addr) \
    asm volatile("ldmatrix.sync.aligned.m8n8.x4.shared.b16 {%0,%1,%2,%3}, [%4];" \
        : "=r"((r)[0]), "=r"((r)[1]), "=r"((r)[2]), "=r"((r)[3]) : "r"(addr))

#define MMA(c, a, b0, b1) \
    asm volatile("mma.sync.aligned.m16n8k16.row.col.f32.bf16.bf16.f32 " \
        "{%0,%1,%2,%3},{%4,%5,%6,%7},{%8,%9},{%0,%1,%2,%3};" \
        : "+f"((c)[0]), "+f"((c)[1]), "+f"((c)[2]), "+f"((c)[3]) \
        : "r"((a)[0]), "r"((a)[1]), "r"((a)[2]), "r"((a)[3]), "r"(b0), "r"(b1))

__device__ __forceinline__ void grid_sync(unsigned target) {
    __threadfence();
    __syncthreads();
    if (threadIdx.x == 0) {
        atomicAdd(&g_bar, 1u);
        unsigned v;
        do {
            asm volatile("ld.global.acquire.gpu.u32 %0, [%1];" : "=r"(v) : "l"(&g_bar));
        } while (v < target);
    }
    __syncthreads();
}

// ---------------- init / convert ----------------
__global__ void init_state() {
    int i = blockIdx.x * blockDim.x + threadIdx.x;
    if (i == 0) g_bar = 0u;
    if (i < NB * HH) {
        g_c0[i] = 0.f; g_c1[i] = 0.f;
        bf16 z = __float2bfloat16(0.f);
        g_h0h[i] = z; g_h0l[i] = z; g_h1h[i] = z; g_h1l[i] = z;
    }
}

#define NW0 ((size_t)G3 * INDIM)
#define NW1 ((size_t)G3 * HH)
#define NX  ((size_t)NB * TT * INDIM)

__global__ void convert_all(const float* __restrict__ x,
    const float* __restrict__ Wx0, const float* __restrict__ Wh0,
    const float* __restrict__ Wx1, const float* __restrict__ Wh1)
{
    size_t idx = (size_t)blockIdx.x * 256 + threadIdx.x;
    float v; bf16 *dh, *dl; size_t o;
    if (idx < NW0) {
        int r = (int)(idx / INDIM), k = (int)(idx % INDIM);
        int orig = r + (r >= HH ? HH : 0);     // skip f-gate rows
        v = Wx0[(size_t)orig * INDIM + k];
        dh = g_Wx0h; dl = g_Wx0l; o = idx;
    } else if (idx < NW0 + 3 * NW1) {
        size_t i2 = idx - NW0;
        int mat = (int)(i2 / NW1);
        size_t i3 = i2 % NW1;
        int r = (int)(i3 / HH), k = (int)(i3 % HH);
        int orig = r + (r >= HH ? HH : 0);
        const float* W = mat == 0 ? Wh0 : (mat == 1 ? Wx1 : Wh1);
        v = W[(size_t)orig * HH + k];
        dh = mat == 0 ? g_Wh0h : (mat == 1 ? g_Wx1h : g_Wh1h);
        dl = mat == 0 ? g_Wh0l : (mat == 1 ? g_Wx1l : g_Wh1l);
        o = i3;
    } else {
        size_t i2 = idx - NW0 - 3 * NW1;
        if (i2 >= NX) return;
        v = x[i2]; dh = g_xh; dl = g_xl; o = i2;
    }
    bf16 h = __float2bfloat16(v);
    dh[o] = h;
    dl[o] = __float2bfloat16(v - __bfloat162float(h));
}

// ---------------- tile loads (512 threads) ----------------
__device__ __forceinline__ void load_W(uint32_t sbase,
    const bf16* __restrict__ Wh, const bf16* __restrict__ Wl, int k0, int ws, int tid)
{
#pragma unroll
    for (int i = 0; i < 2; i++) {
        int seg = tid + i * NTHREADS;          // 0..1023: 128 rows x 8 segs
        int row = seg >> 3, sc = seg & 7;
        uint32_t so = SWZ((uint32_t)(row * 128 + sc * 16));
        size_t off = (size_t)row * ws + k0 + sc * 8;
        cp16(sbase + OFF_WH + so, Wh + off);
        cp16(sbase + OFF_WL + so, Wl + off);
    }
}
__device__ __forceinline__ void load_B(uint32_t sbase,
    const bf16* __restrict__ Bh, const bf16* __restrict__ Bl, int k0, int bs, int tid)
{
    int row = tid >> 3, sc = tid & 7;          // 64 rows x 8 segs = 512
    uint32_t so = SWZ((uint32_t)(row * 128 + sc * 16));
    size_t off = (size_t)row * bs + k0 + sc * 8;
    cp16(sbase + OFF_BH + so, Bh + off);
    cp16(sbase + OFF_BL + so, Bl + off);
}

// ---------------- warp MMA (16 warps: warpM 0..3 x warpN 0..3) ----------------
__device__ __forceinline__ void compute_chunk(uint32_t stage, float acc[2][2][4],
                                              int lane, int warpM, int warpN)
{
#pragma unroll
    for (int kk = 0; kk < 4; kk++) {
        const int kByte = kk * 32;
        uint32_t ah[2][4], al[2][4];
#pragma unroll
        for (int mt = 0; mt < 2; mt++) {
            int row = warpM * 32 + mt * 16 + (lane & 7) + ((lane >> 3) & 1) * 8;
            int col = kByte + ((lane >> 4) << 4);
            uint32_t a = SWZ((uint32_t)(row * 128 + col));
            LDSM4(ah[mt], stage + OFF_WH + a);
            LDSM4(al[mt], stage + OFF_WL + a);
        }
        uint32_t bh[4], bl[4];
        {
            int row = warpN * 16 + (lane & 7) + ((lane >> 4) & 1) * 8;
            int col = kByte + (((lane >> 3) & 1) << 4);
            uint32_t a = SWZ((uint32_t)(row * 128 + col));
            LDSM4(bh, stage + OFF_BH + a);
            LDSM4(bl, stage + OFF_BL + a);
        }
#pragma unroll
        for (int mt = 0; mt < 2; mt++)
#pragma unroll
            for (int nt = 0; nt < 2; nt++) {
                MMA(acc[mt][nt], ah[mt], bh[nt * 2], bh[nt * 2 + 1]);
                MMA(acc[mt][nt], ah[mt], bl[nt * 2], bl[nt * 2 + 1]);
                MMA(acc[mt][nt], al[mt], bh[nt * 2], bh[nt * 2 + 1]);
            }
    }
}

// pf: 0 = load all of chunk lo, 1 = W prefetched, 2 = W+B prefetched
template <typename F>
__device__ __forceinline__ void gemm_tile(uint32_t tiles, int lo, int NC, int pf,
                                          F&& get, float acc[2][2][4])
{
    const int tid = threadIdx.x;
    const int lane = tid & 31, wid = tid >> 5;
    const int warpM = wid & 3, warpN = wid >> 2;

    auto ld_full = [&](int c) {   // c local
        const bf16 *Wh, *Wl, *Bh, *Bl; int k0, ws, bs;
        get(lo + c, Wh, Wl, Bh, Bl, k0, ws, bs);
        uint32_t sb = tiles + (c % 3) * STAGE_BYTES;
        load_W(sb, Wh, Wl, k0, ws, tid);
        load_B(sb, Bh, Bl, k0, bs, tid);
        CP_COMMIT();
    };
    {   // chunk 0: respect prefetch flag; commit collects prefetched cp.asyncs
        const bf16 *Wh, *Wl, *Bh, *Bl; int k0, ws, bs;
        get(lo, Wh, Wl, Bh, Bl, k0, ws, bs);
        if (pf < 1) load_W(tiles, Wh, Wl, k0, ws, tid);
        if (pf < 2) load_B(tiles, Bh, Bl, k0, bs, tid);
        CP_COMMIT();
    }
    if (NC > 1) ld_full(1);
    for (int c = 0; c < NC; c++) {
        if (c + 1 < NC) { asm volatile("cp.async.wait_group 1;" ::: "memory"); }
        else            { asm volatile("cp.async.wait_group 0;" ::: "memory"); }
        __syncthreads();                     // stage c visible to all; stage c-1 free
        if (c + 2 < NC) ld_full(c + 2);      // into stage (c-1)%3 (freed)
        compute_chunk(tiles + (c % 3) * STAGE_BYTES, acc, lane, warpM, warpN);
    }
    __syncthreads();                         // protect stage0 for cross-phase prefetch
}

// ---------------- chunk pointer logic (recurrent) ----------------
template <int LAYER>
__device__ __forceinline__ void get_rec(int col0, int c,
    const bf16*& Wh, const bf16*& Wl, const bf16*& Bh, const bf16*& Bl, int& k0)
{
    if (LAYER == 0) {
        k0 = c * 64;
        Wh = g_Wh0h + (size_t)col0 * HH; Wl = g_Wh0l + (size_t)col0 * HH;
        Bh = g_h0h; Bl = g_h0l;
    } else if (c < 16) {
        k0 = c * 64;
        Wh = g_Wx1h + (size_t)col0 * HH; Wl = g_Wx1l + (size_t)col0 * HH;
        Bh = g_h0h; Bl = g_h0l;
    } else {
        k0 = (c - 16) * 64;
        Wh = g_Wh1h + (size_t)col0 * HH; Wl = g_Wh1l + (size_t)col0 * HH;
        Bh = g_h1h; Bl = g_h1l;
    }
}

// prefetch W (and optionally B) of chunk lo of phase LAYER into stage 0, NO commit
template <int LAYER>
__device__ __forceinline__ void prefetch0(uint32_t tiles, bool doB) {
    const int ct = blockIdx.x / SPLITS;
    const int sp = blockIdx.x % SPLITS;
    const int col0 = ct * 128;
    const int CH = (LAYER == 0) ? 16 : 32;
    const int lo = (sp * CH) / SPLITS;
    const bf16 *Wh, *Wl, *Bh, *Bl; int k0;
    get_rec<LAYER>(col0, lo, Wh, Wl, Bh, Bl, k0);
    load_W(tiles, Wh, Wl, k0, HH, threadIdx.x);
    if (doB) load_B(tiles, Bh, Bl, k0, HH, threadIdx.x);
}

// ---------------- precompute gx0 ----------------
__global__ __launch_bounds__(NTHREADS, 1) void precompute_tc(const float* __restrict__ b0) {
    extern __shared__ char smem[];
    uint32_t tiles = smem_u32(smem);
    const int ct = blockIdx.x % 24;
    const int nt0 = (blockIdx.x / 24) * 64;
    const int col0 = ct * 128;

    float acc[2][2][4];
#pragma unroll
    for (int i = 0; i < 2; i++)
#pragma unroll
        for (int j = 0; j < 2; j++)
#pragma unroll
            for (int k = 0; k < 4; k++) acc[i][j][k] = 0.f;

    auto get = [&](int c, const bf16*& Wh, const bf16*& Wl,
                   const bf16*& Bh, const bf16*& Bl, int& k0, int& ws, int& bs) {
        ws = INDIM; bs = INDIM; k0 = c * 64;
        Wh = g_Wx0h + (size_t)col0 * INDIM; Wl = g_Wx0l + (size_t)col0 * INDIM;
        Bh = g_xh + (size_t)nt0 * INDIM;    Bl = g_xl + (size_t)nt0 * INDIM;
    };
    gemm_tile(tiles, 0, INDIM / 64, 0, get, acc);

    const int lane = threadIdx.x & 31, wid = threadIdx.x >> 5;
    const int warpM = wid & 3, warpN = wid >> 2;
    const int g = lane >> 2, tig = lane & 3;
#pragma unroll
    for (int mt = 0; mt < 2; mt++) {
        int colA = col0 + warpM * 32 + mt * 16 + g;
        float bias0 = b0[colA + (colA >= HH ? HH : 0)];
        float bias8 = b0[colA + 8 + (colA + 8 >= HH ? HH : 0)];
#pragma unroll
        for (int nt = 0; nt < 2; nt++) {
            int r = nt0 + warpN * 16 + nt * 8 + tig * 2;
            g_gx0[(size_t)r * G3 + colA] = acc[mt][nt][0] + bias0;
            g_gx0[(size_t)(r + 1) * G3 + colA] = acc[mt][nt][1] + bias0;
            g_gx0[(size_t)r * G3 + colA + 8] = acc[mt][nt][2] + bias8;
            g_gx0[(size_t)(r + 1) * G3 + colA + 8] = acc[mt][nt][3] + bias8;
        }
    }
}

// ---------------- recurrent phases ----------------
template <int LAYER>
__device__ __forceinline__ void gemm_phase(uint32_t tiles, float* __restrict__ part, int pf) {
    const int ct = blockIdx.x / SPLITS;
    const int sp = blockIdx.x % SPLITS;
    const int col0 = ct * 128;
    const int CH = (LAYER == 0) ? 16 : 32;
    const int lo = (sp * CH) / SPLITS;
    const int hi = ((sp + 1) * CH) / SPLITS;

    float acc[2][2][4];
#pragma unroll
    for (int i = 0; i < 2; i++)
#pragma unroll
        for (int j = 0; j < 2; j++)
#pragma unroll
            for (int k = 0; k < 4; k++) acc[i][j][k] = 0.f;

    auto get = [&](int c, const bf16*& Wh, const bf16*& Wl,
                   const bf16*& Bh, const bf16*& Bl, int& k0, int& ws, int& bs) {
        ws = HH; bs = HH;
        get_rec<LAYER>(col0, c, Wh, Wl, Bh, Bl, k0);
    };
    gemm_tile(tiles, lo, hi - lo, pf, get, acc);

    const int lane = threadIdx.x & 31, wid = threadIdx.x >> 5;
    const int warpM = wid & 3, warpN = wid >> 2;
    const int g = lane >> 2, tig = lane & 3;
#pragma unroll
    for (int mt = 0; mt < 2; mt++) {
        int colA = col0 + warpM * 32 + mt * 16 + g;
#pragma unroll
        for (int nt = 0; nt < 2; nt++) {
            int b = warpN * 16 + nt * 8 + tig * 2;
            float* p0 = part + ((size_t)sp * NB + b) * G3;
            p0[colA] = acc[mt][nt][0];
            p0[G3 + colA] = acc[mt][nt][1];
            p0[colA + 8] = acc[mt][nt][2];
            p0[G3 + colA + 8] = acc[mt][nt][3];
        }
    }
}

template <int LAYER>
__device__ __forceinline__ void pointwise(const float* __restrict__ part,
    const float* __restrict__ bias, const float* __restrict__ Wc,
    float* __restrict__ out, int t)
{
    int cell = blockIdx.x * NTHREADS + threadIdx.x;
    if (cell >= NB * HH) return;
    int b = cell >> 10, j = cell & (HH - 1);
    float si = 0.f, sg = 0.f, so = 0.f;
#pragma unroll
    for (int sp = 0; sp < SPLITS; sp++) {
        const float* p = part + ((size_t)sp * NB + b) * G3 + j;
        si += p[0]; sg += p[HH]; so += p[2 * HH];
    }
    float pi, pg, po;
    if (LAYER == 0) {
        const float* gx = &g_gx0[((size_t)b * TT + t) * G3 + j];
        pi = si + gx[0]; pg = sg + gx[HH]; po = so + gx[2 * HH];
    } else {
        pi = si + bias[j]; pg = sg + bias[2 * HH + j]; po = so + bias[3 * HH + j];
    }
    float* cb = (LAYER == 0) ? g_c0 : g_c1;
    float c = cb[cell];
    float ig = sigmoid_(pi + Wc[j] * c);
    float gg = tanh_(pg);
    float og = sigmoid_(po + Wc[2 * HH + j] * c);
    float cn = gg * (c + ig);      // faithful: forget gate unused
    float hn = og * tanh_(c);      // faithful: uses OLD cell state
    cb[cell] = cn;
    bf16 hh = __float2bfloat16(hn);
    bf16 hl = __float2bfloat16(hn - __bfloat162float(hh));
    if (LAYER == 0) {
        g_h0h[cell] = hh; g_h0l[cell] = hl;
    } else {
        g_h1h[cell] = hh; g_h1l[cell] = hl;
        out[((size_t)b * TT + t) * HH + j] = hn;
        if (t == TT - 1) {
            out[(size_t)NB * TT * HH + cell] = hn;
            out[(size_t)NB * TT * HH + NB * HH + cell] = cn;
        }
    }
}

__global__ __launch_bounds__(NTHREADS, 1) void lstm_persistent(
    const float* __restrict__ b1, const float* __restrict__ Wc0,
    const float* __restrict__ Wc1, float* __restrict__ out)
{
    extern __shared__ char smem[];
    uint32_t tiles = smem_u32(smem);
    unsigned gen = 0;
    int pf0 = 0;
    for (int t = 0; t < TT; t++) {
        gemm_phase<0>(tiles, g_part0, pf0);
        prefetch0<1>(tiles, false);            // W of gemm1 chunk0 (static) -> stage0
        grid_sync(++gen * GRID);
        pointwise<0>(g_part0, nullptr, Wc0, out, t);
        grid_sync(++gen * GRID);
        gemm_phase<1>(tiles, g_part1, 1);      // W prefetched; B loaded now
        if (t + 1 < TT) {
            prefetch0<0>(tiles, true);         // W=Wh0, B=h0(t) final since sync#2
            pf0 = 2;
        }
        grid_sync(++gen * GRID);
        pointwise<1>(g_part1, b1, Wc1, out, t);
        // pw<1>(t) vs gemm<0>(t+1): disjoint buffers; syncs #1/#2 of step t+1
        // order pw<1>(t) before gemm<1>(t+1)'s h1 reads.
    }
}

// ---------------- host launch ----------------
extern "C" void kernel_launch(void* const* d_in, const int* in_sizes, int n_in,
                              void* d_out, int out_size) {
    const float* x   = (const float*)d_in[0];
    const float* Wx0 = (const float*)d_in[1];
    const float* Wh0 = (const float*)d_in[2];
    const float* b0  = (const float*)d_in[3];
    const float* Wc0 = (const float*)d_in[4];
    const float* Wx1 = (const float*)d_in[5];
    const float* Wh1 = (const float*)d_in[6];
    const float* b1  = (const float*)d_in[7];
    const float* Wc1 = (const float*)d_in[8];
    float* out = (float*)d_out;

    cudaFuncSetAttribute(precompute_tc,
                         cudaFuncAttributeMaxDynamicSharedMemorySize, SMEM_TOTAL);
    cudaFuncSetAttribute(lstm_persistent,
                         cudaFuncAttributeMaxDynamicSharedMemorySize, SMEM_TOTAL);

    size_t total_conv = NW0 + 3 * NW1 + NX;
    int conv_blocks = (int)((total_conv + 255) / 256);

    init_state<<<256, 256>>>();
    convert_all<<<conv_blocks, 256>>>(x, Wx0, Wh0, Wx1, Wh1);
    precompute_tc<<<24 * (NB * TT / 64), NTHREADS, SMEM_TOTAL>>>(b0);
    lstm_persistent<<<GRID, NTHREADS, SMEM_TOTAL>>>(b1, Wc0, Wc1, out);
}